// round 15
// baseline (speedup 1.0000x reference)
#include <cuda_runtime.h>
#include <cuda_bf16.h>
#include <cuda_fp16.h>
#include <cstdint>

#define NN 100000
#define EE 1600000
#define FIN 128
#define HID 64
#define NG 512
#define BN_EPS_F 1e-5f

#define SCAN_CHUNK 1024
#define NCHUNK ((NN + SCAN_CHUNK - 1) / SCAN_CHUNK)   // 98

// mma.sync in_proj tile: SMEM bf16 rows padded (K=128 -> 136 elems = 272B)
#define RSTRB 272
#define XH_OFF 0
#define XL_OFF 34816
#define WH_OFF 69632
#define WL_OFF 87040
#define MMA_SMEM 104448

// K=64 mma tiles (mid / final): bf16 rows padded to 72 elems = 144B
#define RST2 144
#define MD_AH 0
#define MD_AL 18432
#define MD_W1H 36864
#define MD_W1L 46080
#define MD_W2H 55296
#define MD_W2L 64512
#define MD_SC 73728
#define MD_SH 73984
#define MD_SMEM 74240
#define FN_AH 0
#define FN_AL 18432
#define FN_WH 36864
#define FN_WL 46080
#define FN_SC 55296
#define FN_SH 55552
#define FN_SMEM 55808

typedef unsigned long long ull;

// Scratch (allocation-free rule: __device__ globals).
// Double-buffered fp16 Y: layer-1 projections in g_Yh, layer-2 in g_Yh2.
// (round-14 bug: mid gathered from AND wrote g_Yh -> cross-block WAR race)
__device__ __align__(16) __half g_Yh[(size_t)NN * HID];
__device__ __align__(16) __half g_Yh2[(size_t)NN * HID];
__device__ int g_cnt[NN];
__device__ int g_scan[NN];
__device__ int g_bsum[NCHUNK];
__device__ int g_rowptr[NN + 1];
__device__ int g_cursor[NN];
__device__ int g_ss[EE];

__device__ __forceinline__ void red_add_v2(float* p, float a, float b) {
    asm volatile("red.global.add.v2.f32 [%0], {%1,%2};"
                 :: "l"(p), "f"(a), "f"(b) : "memory");
}

__device__ __forceinline__ uint32_t smem_u32(const void* p) {
    uint32_t a;
    asm("{ .reg .u64 t; cvta.to.shared.u64 t, %1; cvt.u32.u64 %0, t; }" : "=r"(a) : "l"(p));
    return a;
}
#define BF2(res, a, b) asm("cvt.rn.satfinite.bf16x2.f32 %0, %1, %2;" : "=r"(res) : "f"(b), "f"(a))

#define LDMX4(r0, r1, r2, r3, addr)                                             \
    asm volatile("ldmatrix.sync.aligned.m8n8.x4.shared.b16 {%0,%1,%2,%3}, [%4];" \
                 : "=r"(r0), "=r"(r1), "=r"(r2), "=r"(r3) : "r"(addr))

#define MMA16816(d, a0, a1, a2, a3, b0, b1)                                     \
    asm volatile("mma.sync.aligned.m16n8k16.row.col.f32.bf16.bf16.f32 "         \
                 "{%0,%1,%2,%3}, {%4,%5,%6,%7}, {%8,%9}, {%0,%1,%2,%3};"        \
                 : "+f"((d)[0]), "+f"((d)[1]), "+f"((d)[2]), "+f"((d)[3])       \
                 : "r"(a0), "r"(a1), "r"(a2), "r"(a3), "r"(b0), "r"(b1))

__device__ __forceinline__ void split8(const float* fv, uint32_t* hp, uint32_t* lp) {
#pragma unroll
    for (int j = 0; j < 4; j++) {
        BF2(hp[j], fv[2 * j], fv[2 * j + 1]);
        float l0 = fv[2 * j]     - __uint_as_float(hp[j] << 16);
        float l1 = fv[2 * j + 1] - __uint_as_float(hp[j] & 0xFFFF0000u);
        BF2(lp[j], l0, l1);
    }
}

// accumulate 8 fp16 (uint4) into acc[0..7]
__device__ __forceinline__ void acc8h(uint4 h, float* acc) {
    float2 p;
    p = __half22float2(*(__half2*)&h.x); acc[0] += p.x; acc[1] += p.y;
    p = __half22float2(*(__half2*)&h.y); acc[2] += p.x; acc[3] += p.y;
    p = __half22float2(*(__half2*)&h.z); acc[4] += p.x; acc[5] += p.y;
    p = __half22float2(*(__half2*)&h.w); acc[6] += p.x; acc[7] += p.y;
}

// fused gather for one (row, half) from Ysrc: acc[32] = bias + Ysrc[row] + sum_nbr, relu
__device__ __forceinline__ void gather_row_half(
    const __half* __restrict__ Ysrc, int gm, int half,
    const float* __restrict__ bias, float* acc)
{
    const uint4* Yh4 = (const uint4*)Ysrc;   // 8 uint4 per 64-feat row
    int qb = half * 4;
    {
        const float4* b4 = (const float4*)(bias + half * 32);
#pragma unroll
        for (int j = 0; j < 8; j++) {
            float4 b = b4[j];
            acc[4 * j] = b.x; acc[4 * j + 1] = b.y; acc[4 * j + 2] = b.z; acc[4 * j + 3] = b.w;
        }
    }
    size_t selfBase = (size_t)gm * 8 + qb;
#pragma unroll
    for (int q = 0; q < 4; q++) acc8h(Yh4[selfBase + q], acc + 8 * q);

    int beg = g_rowptr[gm], end = g_rowptr[gm + 1];
#pragma unroll 2
    for (int e = beg; e < end; e++) {
        size_t sBase = (size_t)g_ss[e] * 8 + qb;
#pragma unroll
        for (int q = 0; q < 4; q++) acc8h(Yh4[sBase + q], acc + 8 * q);
    }
#pragma unroll
    for (int j = 0; j < 32; j++) acc[j] = fmaxf(acc[j], 0.f);
}

// ---------------------------------------------------------------- fused zero
__global__ void k_zero_all(float* __restrict__ out) {
    int i = blockIdx.x * blockDim.x + threadIdx.x;
    if (i < NG * HID) out[i] = 0.f;
    if (i < NN) g_cnt[i] = 0;
}

// ---------------------------------------------------------------- CSR build
__global__ void k_hist(const int* __restrict__ ei) {
    int e = blockIdx.x * blockDim.x + threadIdx.x;
    if (e < EE) atomicAdd(&g_cnt[ei[EE + e]], 1);
}

__global__ __launch_bounds__(SCAN_CHUNK) void k_scan1() {
    __shared__ int s[SCAN_CHUNK];
    int tid = threadIdx.x;
    int i = blockIdx.x * SCAN_CHUNK + tid;
    int v = (i < NN) ? g_cnt[i] : 0;
    s[tid] = v;
    __syncthreads();
#pragma unroll
    for (int off = 1; off < SCAN_CHUNK; off <<= 1) {
        int t = (tid >= off) ? s[tid - off] : 0;
        __syncthreads();
        s[tid] += t;
        __syncthreads();
    }
    if (i < NN) g_scan[i] = s[tid];
    if (tid == SCAN_CHUNK - 1) g_bsum[blockIdx.x] = s[tid];
}

__global__ void k_scan3f() {
    __shared__ int boff[NCHUNK];
    if (threadIdx.x == 0) {
        int run = 0;
#pragma unroll 2
        for (int c = 0; c < NCHUNK; c++) { int t = g_bsum[c]; boff[c] = run; run += t; }
    }
    __syncthreads();
    int i = blockIdx.x * blockDim.x + threadIdx.x;
    if (i >= NN) return;
    int incl = g_scan[i] + boff[i / SCAN_CHUNK];
    g_rowptr[i + 1] = incl;
    g_cursor[i] = incl - g_cnt[i];
    if (i == 0) g_rowptr[0] = 0;
}

__global__ void k_reorder(const int* __restrict__ ei) {
    int e = blockIdx.x * blockDim.x + threadIdx.x;
    if (e >= EE) return;
    int d = ei[EE + e];
    int pos = atomicAdd(&g_cursor[d], 1);
    g_ss[pos] = ei[e];
}

// ================================================================ in_proj via mma.sync
__global__ __launch_bounds__(256, 2) void k_in_proj_mma(
    const float* __restrict__ x, const float* __restrict__ W)
{
    extern __shared__ char smc[];
    uint32_t sb = smem_u32(smc);
    int tid = threadIdx.x;
    int w = tid >> 5, l = tid & 31;
    int m0 = blockIdx.x * 128;

    {
        int row = tid >> 1, half = tid & 1;
        int gm = m0 + row;
        bool ok = gm < NN;
        const float4* xr = (const float4*)(x + (size_t)gm * FIN + half * 64);
        int rbase = row * RSTRB + half * 128;
#pragma unroll
        for (int c = 0; c < 8; c++) {
            float4 f0 = ok ? xr[2 * c] : make_float4(0.f, 0.f, 0.f, 0.f);
            float4 f1 = ok ? xr[2 * c + 1] : make_float4(0.f, 0.f, 0.f, 0.f);
            float fv[8] = {f0.x, f0.y, f0.z, f0.w, f1.x, f1.y, f1.z, f1.w};
            uint32_t hp[4], lp[4];
            split8(fv, hp, lp);
            *(uint4*)(smc + XH_OFF + rbase + c * 16) = make_uint4(hp[0], hp[1], hp[2], hp[3]);
            *(uint4*)(smc + XL_OFF + rbase + c * 16) = make_uint4(lp[0], lp[1], lp[2], lp[3]);
        }
    }
    {
        int row = tid >> 2, q = tid & 3;
        const float4* wr = (const float4*)(W + (size_t)row * FIN + q * 32);
        int rbase = row * RSTRB + q * 64;
#pragma unroll
        for (int c = 0; c < 4; c++) {
            float4 f0 = wr[2 * c];
            float4 f1 = wr[2 * c + 1];
            float fv[8] = {f0.x, f0.y, f0.z, f0.w, f1.x, f1.y, f1.z, f1.w};
            uint32_t hp[4], lp[4];
            split8(fv, hp, lp);
            *(uint4*)(smc + WH_OFF + rbase + c * 16) = make_uint4(hp[0], hp[1], hp[2], hp[3]);
            *(uint4*)(smc + WL_OFF + rbase + c * 16) = make_uint4(lp[0], lp[1], lp[2], lp[3]);
        }
    }
    __syncthreads();

    uint32_t aAddr = sb + (uint32_t)((16 * w + (l & 15)) * RSTRB + (l >> 4) * 16);
    int bN = (l & 7) + ((l >> 4) << 3);
    int bKc = (l >> 3) & 1;
    uint32_t bAddr = sb + (uint32_t)(bN * RSTRB + bKc * 16);

    float D[8][4];
#pragma unroll
    for (int nc = 0; nc < 8; nc++)
#pragma unroll
        for (int j = 0; j < 4; j++) D[nc][j] = 0.f;

#pragma unroll
    for (int ks = 0; ks < 8; ks++) {
        uint32_t ko = ks * 32;
        uint32_t ah0, ah1, ah2, ah3, al0, al1, al2, al3;
        LDMX4(ah0, ah1, ah2, ah3, aAddr + XH_OFF + ko);
        LDMX4(al0, al1, al2, al3, aAddr + XL_OFF + ko);
#pragma unroll
        for (int g = 0; g < 4; g++) {
            uint32_t gb = bAddr + (uint32_t)(g * 16 * RSTRB) + ko;
            uint32_t bh0, bh1, bh2, bh3, bl0, bl1, bl2, bl3;
            LDMX4(bh0, bh1, bh2, bh3, gb + WH_OFF);
            LDMX4(bl0, bl1, bl2, bl3, gb + WL_OFF);
            MMA16816(D[2 * g],     ah0, ah1, ah2, ah3, bh0, bh1);
            MMA16816(D[2 * g],     ah0, ah1, ah2, ah3, bl0, bl1);
            MMA16816(D[2 * g],     al0, al1, al2, al3, bh0, bh1);
            MMA16816(D[2 * g + 1], ah0, ah1, ah2, ah3, bh2, bh3);
            MMA16816(D[2 * g + 1], ah0, ah1, ah2, ah3, bl2, bl3);
            MMA16816(D[2 * g + 1], al0, al1, al2, al3, bh2, bh3);
        }
    }

    int r0 = m0 + 16 * w + (l >> 2);
    int r1 = r0 + 8;
#pragma unroll
    for (int nc = 0; nc < 8; nc++) {
        int col = nc * 8 + (l & 3) * 2;
        if (r0 < NN) *(__half2*)(g_Yh + (size_t)r0 * HID + col) = __floats2half2_rn(D[nc][0], D[nc][1]);
        if (r1 < NN) *(__half2*)(g_Yh + (size_t)r1 * HID + col) = __floats2half2_rn(D[nc][2], D[nc][3]);
    }
}

// ================================================================ k_mid (fused gather + 2 GEMMs)
// gathers from g_Yh, writes Y2 to g_Yh2 (no aliasing)
__global__ __launch_bounds__(256, 2) void k_mid_mma(
    const float* __restrict__ b1a,
    const float* __restrict__ W1b, const float* __restrict__ b1b,
    const float* __restrict__ g1,  const float* __restrict__ be1,
    const float* __restrict__ m1,  const float* __restrict__ v1,
    const float* __restrict__ W2a)
{
    extern __shared__ char smc[];
    uint32_t sb = smem_u32(smc);
    float* scp = (float*)(smc + MD_SC);
    float* shp = (float*)(smc + MD_SH);
    int tid = threadIdx.x;
    int w = tid >> 5, l = tid & 31;
    int m0 = blockIdx.x * 128;

    {
        int row = tid >> 1, half = tid & 1;
        int gm = m0 + row;
        int rbase = row * RST2 + half * 64;
        float acc[32];
        if (gm < NN) {
            gather_row_half(g_Yh, gm, half, b1a, acc);
        } else {
#pragma unroll
            for (int j = 0; j < 32; j++) acc[j] = 0.f;
        }
#pragma unroll
        for (int c = 0; c < 4; c++) {
            uint32_t hp[4], lp[4];
            split8(acc + 8 * c, hp, lp);
            *(uint4*)(smc + MD_AH + rbase + c * 16) = make_uint4(hp[0], hp[1], hp[2], hp[3]);
            *(uint4*)(smc + MD_AL + rbase + c * 16) = make_uint4(lp[0], lp[1], lp[2], lp[3]);
        }
    }
    {
        int row = tid >> 2, q = tid & 3;
        const float4* w1r = (const float4*)(W1b + (size_t)row * HID + q * 16);
        const float4* w2r = (const float4*)(W2a + (size_t)row * HID + q * 16);
#pragma unroll
        for (int c = 0; c < 2; c++) {
            int rb = row * RST2 + q * 32 + c * 16;
            float4 f0 = w1r[2 * c], f1 = w1r[2 * c + 1];
            float fv[8] = {f0.x, f0.y, f0.z, f0.w, f1.x, f1.y, f1.z, f1.w};
            uint32_t hp[4], lp[4];
            split8(fv, hp, lp);
            *(uint4*)(smc + MD_W1H + rb) = make_uint4(hp[0], hp[1], hp[2], hp[3]);
            *(uint4*)(smc + MD_W1L + rb) = make_uint4(lp[0], lp[1], lp[2], lp[3]);
            f0 = w2r[2 * c]; f1 = w2r[2 * c + 1];
            float gv[8] = {f0.x, f0.y, f0.z, f0.w, f1.x, f1.y, f1.z, f1.w};
            split8(gv, hp, lp);
            *(uint4*)(smc + MD_W2H + rb) = make_uint4(hp[0], hp[1], hp[2], hp[3]);
            *(uint4*)(smc + MD_W2L + rb) = make_uint4(lp[0], lp[1], lp[2], lp[3]);
        }
    }
    if (tid < HID) {
        float s = g1[tid] * rsqrtf(v1[tid] + BN_EPS_F);
        scp[tid] = s;
        shp[tid] = (b1b[tid] - m1[tid]) * s + be1[tid];
    }
    __syncthreads();

    uint32_t aAddr = sb + (uint32_t)((16 * w + (l & 15)) * RST2 + (l >> 4) * 16);
    int bN = (l & 7) + ((l >> 4) << 3);
    int bKc = (l >> 3) & 1;
    uint32_t bAddr = sb + (uint32_t)(bN * RST2 + bKc * 16);

    float D[8][4];
#pragma unroll
    for (int nc = 0; nc < 8; nc++)
#pragma unroll
        for (int j = 0; j < 4; j++) D[nc][j] = 0.f;

#pragma unroll
    for (int ks = 0; ks < 4; ks++) {
        uint32_t ko = ks * 32;
        uint32_t ah0, ah1, ah2, ah3, al0, al1, al2, al3;
        LDMX4(ah0, ah1, ah2, ah3, aAddr + MD_AH + ko);
        LDMX4(al0, al1, al2, al3, aAddr + MD_AL + ko);
#pragma unroll
        for (int g = 0; g < 4; g++) {
            uint32_t gb = bAddr + (uint32_t)(g * 16 * RST2) + ko;
            uint32_t bh0, bh1, bh2, bh3, bl0, bl1, bl2, bl3;
            LDMX4(bh0, bh1, bh2, bh3, gb + MD_W1H);
            LDMX4(bl0, bl1, bl2, bl3, gb + MD_W1L);
            MMA16816(D[2 * g],     ah0, ah1, ah2, ah3, bh0, bh1);
            MMA16816(D[2 * g],     ah0, ah1, ah2, ah3, bl0, bl1);
            MMA16816(D[2 * g],     al0, al1, al2, al3, bh0, bh1);
            MMA16816(D[2 * g + 1], ah0, ah1, ah2, ah3, bh2, bh3);
            MMA16816(D[2 * g + 1], ah0, ah1, ah2, ah3, bl2, bl3);
            MMA16816(D[2 * g + 1], al0, al1, al2, al3, bh2, bh3);
        }
    }

    uint32_t ahi[4][4], alo[4][4];
    {
        int t2 = (l & 3) * 2;
#pragma unroll
        for (int nc = 0; nc < 8; nc++) {
            int col = nc * 8 + t2;
            float s0 = scp[col], s1 = scp[col + 1];
            float t0 = shp[col], t1 = shp[col + 1];
            D[nc][0] = fmaxf(fmaf(D[nc][0], s0, t0), 0.f);
            D[nc][1] = fmaxf(fmaf(D[nc][1], s1, t1), 0.f);
            D[nc][2] = fmaxf(fmaf(D[nc][2], s0, t0), 0.f);
            D[nc][3] = fmaxf(fmaf(D[nc][3], s1, t1), 0.f);
        }
#pragma unroll
        for (int kc = 0; kc < 4; kc++) {
#pragma unroll
            for (int j = 0; j < 4; j++) {
                float h0 = D[2 * kc + (j >> 1)][(j & 1) * 2 + 0];
                float h1 = D[2 * kc + (j >> 1)][(j & 1) * 2 + 1];
                uint32_t hp;
                BF2(hp, h0, h1);
                float l0 = h0 - __uint_as_float(hp << 16);
                float l1 = h1 - __uint_as_float(hp & 0xFFFF0000u);
                uint32_t lp;
                BF2(lp, l0, l1);
                ahi[kc][j] = hp;
                alo[kc][j] = lp;
            }
        }
    }

    float D2[8][4];
#pragma unroll
    for (int nc = 0; nc < 8; nc++)
#pragma unroll
        for (int j = 0; j < 4; j++) D2[nc][j] = 0.f;

#pragma unroll
    for (int kc = 0; kc < 4; kc++) {
        uint32_t ko = kc * 32;
#pragma unroll
        for (int g = 0; g < 4; g++) {
            uint32_t gb = bAddr + (uint32_t)(g * 16 * RST2) + ko;
            uint32_t bh0, bh1, bh2, bh3, bl0, bl1, bl2, bl3;
            LDMX4(bh0, bh1, bh2, bh3, gb + MD_W2H);
            LDMX4(bl0, bl1, bl2, bl3, gb + MD_W2L);
            MMA16816(D2[2 * g],     ahi[kc][0], ahi[kc][1], ahi[kc][2], ahi[kc][3], bh0, bh1);
            MMA16816(D2[2 * g],     ahi[kc][0], ahi[kc][1], ahi[kc][2], ahi[kc][3], bl0, bl1);
            MMA16816(D2[2 * g],     alo[kc][0], alo[kc][1], alo[kc][2], alo[kc][3], bh0, bh1);
            MMA16816(D2[2 * g + 1], ahi[kc][0], ahi[kc][1], ahi[kc][2], ahi[kc][3], bh2, bh3);
            MMA16816(D2[2 * g + 1], ahi[kc][0], ahi[kc][1], ahi[kc][2], ahi[kc][3], bl2, bl3);
            MMA16816(D2[2 * g + 1], alo[kc][0], alo[kc][1], alo[kc][2], alo[kc][3], bh2, bh3);
        }
    }

    int r0 = m0 + 16 * w + (l >> 2);
    int r1 = r0 + 8;
#pragma unroll
    for (int nc = 0; nc < 8; nc++) {
        int col = nc * 8 + (l & 3) * 2;
        if (r0 < NN) *(__half2*)(g_Yh2 + (size_t)r0 * HID + col) = __floats2half2_rn(D2[nc][0], D2[nc][1]);
        if (r1 < NN) *(__half2*)(g_Yh2 + (size_t)r1 * HID + col) = __floats2half2_rn(D2[nc][2], D2[nc][3]);
    }
}

// ================================================================ k_final (fused gather + GEMM + pool)
// gathers from g_Yh2
__global__ __launch_bounds__(256, 2) void k_final_mma(
    const float* __restrict__ b2a,
    const float* __restrict__ W2b, const float* __restrict__ bb,
    const float* __restrict__ ga,  const float* __restrict__ be,
    const float* __restrict__ mm,  const float* __restrict__ vv,
    const int* __restrict__ batch, float* __restrict__ out)
{
    extern __shared__ char smc[];
    uint32_t sb = smem_u32(smc);
    float* scp = (float*)(smc + FN_SC);
    float* shp = (float*)(smc + FN_SH);
    int tid = threadIdx.x;
    int w = tid >> 5, l = tid & 31;
    int m0 = blockIdx.x * 128;

    {
        int row = tid >> 1, half = tid & 1;
        int gm = m0 + row;
        int rbase = row * RST2 + half * 64;
        float acc[32];
        if (gm < NN) {
            gather_row_half(g_Yh2, gm, half, b2a, acc);
        } else {
#pragma unroll
            for (int j = 0; j < 32; j++) acc[j] = 0.f;
        }
#pragma unroll
        for (int c = 0; c < 4; c++) {
            uint32_t hp[4], lp[4];
            split8(acc + 8 * c, hp, lp);
            *(uint4*)(smc + FN_AH + rbase + c * 16) = make_uint4(hp[0], hp[1], hp[2], hp[3]);
            *(uint4*)(smc + FN_AL + rbase + c * 16) = make_uint4(lp[0], lp[1], lp[2], lp[3]);
        }
    }
    {
        int row = tid >> 2, q = tid & 3;
        const float4* wr = (const float4*)(W2b + (size_t)row * HID + q * 16);
#pragma unroll
        for (int c = 0; c < 2; c++) {
            int rb = row * RST2 + q * 32 + c * 16;
            float4 f0 = wr[2 * c], f1 = wr[2 * c + 1];
            float fv[8] = {f0.x, f0.y, f0.z, f0.w, f1.x, f1.y, f1.z, f1.w};
            uint32_t hp[4], lp[4];
            split8(fv, hp, lp);
            *(uint4*)(smc + FN_WH + rb) = make_uint4(hp[0], hp[1], hp[2], hp[3]);
            *(uint4*)(smc + FN_WL + rb) = make_uint4(lp[0], lp[1], lp[2], lp[3]);
        }
    }
    if (tid < HID) {
        float s = ga[tid] * rsqrtf(vv[tid] + BN_EPS_F);
        scp[tid] = s;
        shp[tid] = (bb[tid] - mm[tid]) * s + be[tid];
    }
    __syncthreads();

    uint32_t aAddr = sb + (uint32_t)((16 * w + (l & 15)) * RST2 + (l >> 4) * 16);
    int bN = (l & 7) + ((l >> 4) << 3);
    int bKc = (l >> 3) & 1;
    uint32_t bAddr = sb + (uint32_t)(bN * RST2 + bKc * 16);

    float D[8][4];
#pragma unroll
    for (int nc = 0; nc < 8; nc++)
#pragma unroll
        for (int j = 0; j < 4; j++) D[nc][j] = 0.f;

#pragma unroll
    for (int ks = 0; ks < 4; ks++) {
        uint32_t ko = ks * 32;
        uint32_t ah0, ah1, ah2, ah3, al0, al1, al2, al3;
        LDMX4(ah0, ah1, ah2, ah3, aAddr + FN_AH + ko);
        LDMX4(al0, al1, al2, al3, aAddr + FN_AL + ko);
#pragma unroll
        for (int g = 0; g < 4; g++) {
            uint32_t gb = bAddr + (uint32_t)(g * 16 * RST2) + ko;
            uint32_t bh0, bh1, bh2, bh3, bl0, bl1, bl2, bl3;
            LDMX4(bh0, bh1, bh2, bh3, gb + FN_WH);
            LDMX4(bl0, bl1, bl2, bl3, gb + FN_WL);
            MMA16816(D[2 * g],     ah0, ah1, ah2, ah3, bh0, bh1);
            MMA16816(D[2 * g],     ah0, ah1, ah2, ah3, bl0, bl1);
            MMA16816(D[2 * g],     al0, al1, al2, al3, bh0, bh1);
            MMA16816(D[2 * g + 1], ah0, ah1, ah2, ah3, bh2, bh3);
            MMA16816(D[2 * g + 1], ah0, ah1, ah2, ah3, bl2, bl3);
            MMA16816(D[2 * g + 1], al0, al1, al2, al3, bh2, bh3);
        }
    }

    int r0 = m0 + 16 * w + (l >> 2);
    int r1 = r0 + 8;
    int gb0 = (r0 < NN) ? batch[r0] : 0;
    int gb1 = (r1 < NN) ? batch[r1] : 0;
    int t2 = (l & 3) * 2;
#pragma unroll
    for (int nc = 0; nc < 8; nc++) {
        int col = nc * 8 + t2;
        float s0 = scp[col], s1 = scp[col + 1];
        float t0 = shp[col], t1 = shp[col + 1];
        if (r0 < NN)
            red_add_v2(out + (size_t)gb0 * HID + col,
                       fmaxf(fmaf(D[nc][0], s0, t0), 0.f),
                       fmaxf(fmaf(D[nc][1], s1, t1), 0.f));
        if (r1 < NN)
            red_add_v2(out + (size_t)gb1 * HID + col,
                       fmaxf(fmaf(D[nc][2], s0, t0), 0.f),
                       fmaxf(fmaf(D[nc][3], s1, t1), 0.f));
    }
}

// ------------------------------------------------- divide by per-graph counts
__global__ void k_div(const int* __restrict__ batch, float* __restrict__ out)
{
    int g = blockIdx.x;
    __shared__ int cnt;
    if (threadIdx.x == 0) {
        int lo = 0, hi = NN;
        while (lo < hi) { int mid = (lo + hi) >> 1; if (batch[mid] < g) lo = mid + 1; else hi = mid; }
        int lo2 = lo, hi2 = NN;
        while (lo2 < hi2) { int mid = (lo2 + hi2) >> 1; if (batch[mid] < g + 1) lo2 = mid + 1; else hi2 = mid; }
        cnt = lo2 - lo;
    }
    __syncthreads();
    float c = (float)(cnt > 1 ? cnt : 1);
    out[(size_t)g * HID + threadIdx.x] /= c;
}

// ---------------------------------------------------------------- launch
extern "C" void kernel_launch(void* const* d_in, const int* in_sizes, int n_in,
                              void* d_out, int out_size)
{
    (void)in_sizes; (void)n_in; (void)out_size;
    const float* x    = (const float*)d_in[0];
    const int*   ei   = (const int*)d_in[1];
    const int*   batch= (const int*)d_in[2];
    const float* W1a  = (const float*)d_in[3];
    const float* b1a  = (const float*)d_in[4];
    const float* W1b  = (const float*)d_in[5];
    const float* b1b  = (const float*)d_in[6];
    const float* g1   = (const float*)d_in[7];
    const float* be1  = (const float*)d_in[8];
    const float* m1   = (const float*)d_in[9];
    const float* v1   = (const float*)d_in[10];
    const float* W2a  = (const float*)d_in[11];
    const float* b2a  = (const float*)d_in[12];
    const float* W2b  = (const float*)d_in[13];
    const float* b2b  = (const float*)d_in[14];
    const float* g2   = (const float*)d_in[15];
    const float* be2  = (const float*)d_in[16];
    const float* m2   = (const float*)d_in[17];
    const float* v2   = (const float*)d_in[18];
    float* out = (float*)d_out;

    static cudaStream_t s2 = nullptr;
    static cudaEvent_t ev0 = nullptr, evA = nullptr;
    if (!s2) {
        cudaStreamCreateWithFlags(&s2, cudaStreamNonBlocking);
        cudaEventCreateWithFlags(&ev0, cudaEventDisableTiming);
        cudaEventCreateWithFlags(&evA, cudaEventDisableTiming);
    }

    cudaFuncSetAttribute(k_in_proj_mma, cudaFuncAttributeMaxDynamicSharedMemorySize, MMA_SMEM);
    cudaFuncSetAttribute(k_mid_mma,     cudaFuncAttributeMaxDynamicSharedMemorySize, MD_SMEM);
    cudaFuncSetAttribute(k_final_mma,   cudaFuncAttributeMaxDynamicSharedMemorySize, FN_SMEM);

    int gemmBlocks = (NN + 127) / 128;             // 782
    int edgeBlocks = (EE + 255) / 256;             // 6250

    // fork: in_proj concurrent with CSR build
    cudaEventRecord(ev0, 0);
    cudaStreamWaitEvent(s2, ev0, 0);
    k_in_proj_mma<<<gemmBlocks, 256, MMA_SMEM, s2>>>(x, W1a);
    cudaEventRecord(evA, s2);

    k_zero_all<<<(NN + 255) / 256, 256>>>(out);
    k_hist<<<edgeBlocks, 256>>>(ei);
    k_scan1<<<NCHUNK, SCAN_CHUNK>>>();
    k_scan3f<<<(NN + 255) / 256, 256>>>();
    k_reorder<<<edgeBlocks, 256>>>(ei);

    cudaStreamWaitEvent(0, evA, 0);

    // layer 1 + mid (gather fused; Yh -> Yh2)
    k_mid_mma<<<gemmBlocks, 256, MD_SMEM>>>(b1a, W1b, b1b, g1, be1, m1, v1, W2a);

    // layer 2 (gather fused from Yh2)
    k_final_mma<<<gemmBlocks, 256, FN_SMEM>>>(b2a, W2b, b2b, g2, be2, m2, v2, batch, out);
    k_div<<<NG, HID>>>(batch, out);
}

// round 16
// speedup vs baseline: 1.0346x; 1.0346x over previous
#include <cuda_runtime.h>
#include <cuda_bf16.h>
#include <cuda_fp16.h>
#include <cstdint>

#define NN 100000
#define EE 1600000
#define FIN 128
#define HID 64
#define NG 512
#define BN_EPS_F 1e-5f

#define SCAN_CHUNK 1024
#define NCHUNK ((NN + SCAN_CHUNK - 1) / SCAN_CHUNK)   // 98

// mma.sync in_proj tile: SMEM bf16 rows padded (K=128 -> 136 elems = 272B)
#define RSTRB 272
#define XH_OFF 0
#define XL_OFF 34816
#define WH_OFF 69632
#define WL_OFF 87040
#define MMA_SMEM 104448

// K=64 mma tiles (mid / final): bf16 rows padded to 72 elems = 144B
#define RST2 144
#define MD_AH 0
#define MD_AL 18432
#define MD_W1H 36864
#define MD_W1L 46080
#define MD_W2H 55296
#define MD_W2L 64512
#define MD_SC 73728
#define MD_SH 73984
#define MD_SMEM 74240
#define FN_AH 0
#define FN_AL 18432
#define FN_WH 36864
#define FN_WL 46080
#define FN_SC 55296
#define FN_SH 55552
#define FN_SMEM 55808

typedef unsigned long long ull;

// Scratch (allocation-free rule: __device__ globals).
__device__ __align__(16) __half g_Yh[(size_t)NN * HID];  // fp16 projected rows (gather source)
__device__ __align__(16) float g_A[(size_t)NN * HID];    // fp32 aggregate
__device__ int g_cnt[NN];
__device__ int g_scan[NN];
__device__ int g_bsum[NCHUNK];
__device__ int g_rowptr[NN + 1];
__device__ int g_cursor[NN];
__device__ int g_ss[EE];

__device__ __forceinline__ void red_add_v2(float* p, float a, float b) {
    asm volatile("red.global.add.v2.f32 [%0], {%1,%2};"
                 :: "l"(p), "f"(a), "f"(b) : "memory");
}

__device__ __forceinline__ uint32_t smem_u32(const void* p) {
    uint32_t a;
    asm("{ .reg .u64 t; cvta.to.shared.u64 t, %1; cvt.u32.u64 %0, t; }" : "=r"(a) : "l"(p));
    return a;
}
#define BF2(res, a, b) asm("cvt.rn.satfinite.bf16x2.f32 %0, %1, %2;" : "=r"(res) : "f"(b), "f"(a))

#define LDMX4(r0, r1, r2, r3, addr)                                             \
    asm volatile("ldmatrix.sync.aligned.m8n8.x4.shared.b16 {%0,%1,%2,%3}, [%4];" \
                 : "=r"(r0), "=r"(r1), "=r"(r2), "=r"(r3) : "r"(addr))

#define MMA16816(d, a0, a1, a2, a3, b0, b1)                                     \
    asm volatile("mma.sync.aligned.m16n8k16.row.col.f32.bf16.bf16.f32 "         \
                 "{%0,%1,%2,%3}, {%4,%5,%6,%7}, {%8,%9}, {%0,%1,%2,%3};"        \
                 : "+f"((d)[0]), "+f"((d)[1]), "+f"((d)[2]), "+f"((d)[3])       \
                 : "r"(a0), "r"(a1), "r"(a2), "r"(a3), "r"(b0), "r"(b1))

__device__ __forceinline__ void split8(const float* fv, uint32_t* hp, uint32_t* lp) {
#pragma unroll
    for (int j = 0; j < 4; j++) {
        BF2(hp[j], fv[2 * j], fv[2 * j + 1]);
        float l0 = fv[2 * j]     - __uint_as_float(hp[j] << 16);
        float l1 = fv[2 * j + 1] - __uint_as_float(hp[j] & 0xFFFF0000u);
        BF2(lp[j], l0, l1);
    }
}

// convert uint4 (8 fp16) and accumulate into acc[0..7]
__device__ __forceinline__ void acc8h(uint4 h, float* acc) {
    float2 p;
    p = __half22float2(*(__half2*)&h.x); acc[0] += p.x; acc[1] += p.y;
    p = __half22float2(*(__half2*)&h.y); acc[2] += p.x; acc[3] += p.y;
    p = __half22float2(*(__half2*)&h.z); acc[4] += p.x; acc[5] += p.y;
    p = __half22float2(*(__half2*)&h.w); acc[6] += p.x; acc[7] += p.y;
}

// ---------------------------------------------------------------- fused zero
__global__ void k_zero_all(float* __restrict__ out) {
    int i = blockIdx.x * blockDim.x + threadIdx.x;
    if (i < NG * HID) out[i] = 0.f;
    if (i < NN) g_cnt[i] = 0;
}

// ---------------------------------------------------------------- CSR build
__global__ void k_hist(const int* __restrict__ ei) {
    int e = blockIdx.x * blockDim.x + threadIdx.x;
    if (e < EE) atomicAdd(&g_cnt[ei[EE + e]], 1);
}

__global__ __launch_bounds__(SCAN_CHUNK) void k_scan1() {
    __shared__ int s[SCAN_CHUNK];
    int tid = threadIdx.x;
    int i = blockIdx.x * SCAN_CHUNK + tid;
    int v = (i < NN) ? g_cnt[i] : 0;
    s[tid] = v;
    __syncthreads();
#pragma unroll
    for (int off = 1; off < SCAN_CHUNK; off <<= 1) {
        int t = (tid >= off) ? s[tid - off] : 0;
        __syncthreads();
        s[tid] += t;
        __syncthreads();
    }
    if (i < NN) g_scan[i] = s[tid];
    if (tid == SCAN_CHUNK - 1) g_bsum[blockIdx.x] = s[tid];
}

__global__ void k_scan3f() {
    __shared__ int boff[NCHUNK];
    if (threadIdx.x == 0) {
        int run = 0;
#pragma unroll 2
        for (int c = 0; c < NCHUNK; c++) { int t = g_bsum[c]; boff[c] = run; run += t; }
    }
    __syncthreads();
    int i = blockIdx.x * blockDim.x + threadIdx.x;
    if (i >= NN) return;
    int incl = g_scan[i] + boff[i / SCAN_CHUNK];
    g_rowptr[i + 1] = incl;
    g_cursor[i] = incl - g_cnt[i];
    if (i == 0) g_rowptr[0] = 0;
}

__global__ void k_reorder(const int* __restrict__ ei) {
    int e = blockIdx.x * blockDim.x + threadIdx.x;
    if (e >= EE) return;
    int d = ei[EE + e];
    int pos = atomicAdd(&g_cursor[d], 1);
    g_ss[pos] = ei[e];
}

// ---------------------------------------------------------------- aggregation (fp16 gather)
// A[n] = Yh[n] + bias + sum_nbr Yh[s]; 8 threads/node, uint4 (8 fp16) per thread.
__global__ __launch_bounds__(256) void k_agg(const float* __restrict__ b) {
    int t = blockIdx.x * 256 + threadIdx.x;
    int n = t >> 3;
    int lane = t & 7;
    if (n >= NN) return;

    const uint4* Yh4 = (const uint4*)g_Yh;
    float acc[8];
    {
        float4 b0 = ((const float4*)b)[2 * lane];
        float4 b1 = ((const float4*)b)[2 * lane + 1];
        acc[0] = b0.x; acc[1] = b0.y; acc[2] = b0.z; acc[3] = b0.w;
        acc[4] = b1.x; acc[5] = b1.y; acc[6] = b1.z; acc[7] = b1.w;
    }
    acc8h(Yh4[(size_t)n * 8 + lane], acc);

    int beg = g_rowptr[n], end = g_rowptr[n + 1];
#pragma unroll 4
    for (int e = beg; e < end; e++) {
        int s = g_ss[e];
        acc8h(Yh4[(size_t)s * 8 + lane], acc);
    }
    float4* A4 = (float4*)g_A + (size_t)n * 16 + 2 * lane;
    A4[0] = make_float4(acc[0], acc[1], acc[2], acc[3]);
    A4[1] = make_float4(acc[4], acc[5], acc[6], acc[7]);
}

// ================================================================ in_proj via mma.sync
// Staging uses batched loads (8x float4 burst -> MLP 8) before conversion.
__global__ __launch_bounds__(256, 2) void k_in_proj_mma(
    const float* __restrict__ x, const float* __restrict__ W)
{
    extern __shared__ char smc[];
    uint32_t sb = smem_u32(smc);
    int tid = threadIdx.x;
    int w = tid >> 5, l = tid & 31;
    int m0 = blockIdx.x * 128;

    // ---- stage A: batch 8 loads, then convert (2 batches)
    {
        int row = tid >> 1, half = tid & 1;
        int gm = m0 + row;
        bool ok = gm < NN;
        const float4* xr = (const float4*)(x + (size_t)gm * FIN + half * 64);
        int rbase = row * RSTRB + half * 128;
#pragma unroll
        for (int b = 0; b < 2; b++) {
            float4 fb[8];
#pragma unroll
            for (int j = 0; j < 8; j++)
                fb[j] = ok ? xr[8 * b + j] : make_float4(0.f, 0.f, 0.f, 0.f);
#pragma unroll
            for (int c0 = 0; c0 < 4; c0++) {
                int c = 4 * b + c0;
                float fv[8] = {fb[2*c0].x, fb[2*c0].y, fb[2*c0].z, fb[2*c0].w,
                               fb[2*c0+1].x, fb[2*c0+1].y, fb[2*c0+1].z, fb[2*c0+1].w};
                uint32_t hp[4], lp[4];
                split8(fv, hp, lp);
                *(uint4*)(smc + XH_OFF + rbase + c * 16) = make_uint4(hp[0], hp[1], hp[2], hp[3]);
                *(uint4*)(smc + XL_OFF + rbase + c * 16) = make_uint4(lp[0], lp[1], lp[2], lp[3]);
            }
        }
    }
    // ---- stage W: batch 8 loads, then convert
    {
        int row = tid >> 2, q = tid & 3;
        const float4* wr = (const float4*)(W + (size_t)row * FIN + q * 32);
        int rbase = row * RSTRB + q * 64;
        float4 wb[8];
#pragma unroll
        for (int j = 0; j < 8; j++) wb[j] = wr[j];
#pragma unroll
        for (int c = 0; c < 4; c++) {
            float fv[8] = {wb[2*c].x, wb[2*c].y, wb[2*c].z, wb[2*c].w,
                           wb[2*c+1].x, wb[2*c+1].y, wb[2*c+1].z, wb[2*c+1].w};
            uint32_t hp[4], lp[4];
            split8(fv, hp, lp);
            *(uint4*)(smc + WH_OFF + rbase + c * 16) = make_uint4(hp[0], hp[1], hp[2], hp[3]);
            *(uint4*)(smc + WL_OFF + rbase + c * 16) = make_uint4(lp[0], lp[1], lp[2], lp[3]);
        }
    }
    __syncthreads();

    uint32_t aAddr = sb + (uint32_t)((16 * w + (l & 15)) * RSTRB + (l >> 4) * 16);
    int bN = (l & 7) + ((l >> 4) << 3);
    int bKc = (l >> 3) & 1;
    uint32_t bAddr = sb + (uint32_t)(bN * RSTRB + bKc * 16);

    float D[8][4];
#pragma unroll
    for (int nc = 0; nc < 8; nc++)
#pragma unroll
        for (int j = 0; j < 4; j++) D[nc][j] = 0.f;

#pragma unroll
    for (int ks = 0; ks < 8; ks++) {
        uint32_t ko = ks * 32;
        uint32_t ah0, ah1, ah2, ah3, al0, al1, al2, al3;
        LDMX4(ah0, ah1, ah2, ah3, aAddr + XH_OFF + ko);
        LDMX4(al0, al1, al2, al3, aAddr + XL_OFF + ko);
#pragma unroll
        for (int g = 0; g < 4; g++) {
            uint32_t gb = bAddr + (uint32_t)(g * 16 * RSTRB) + ko;
            uint32_t bh0, bh1, bh2, bh3, bl0, bl1, bl2, bl3;
            LDMX4(bh0, bh1, bh2, bh3, gb + WH_OFF);
            LDMX4(bl0, bl1, bl2, bl3, gb + WL_OFF);
            MMA16816(D[2 * g],     ah0, ah1, ah2, ah3, bh0, bh1);
            MMA16816(D[2 * g],     ah0, ah1, ah2, ah3, bl0, bl1);
            MMA16816(D[2 * g],     al0, al1, al2, al3, bh0, bh1);
            MMA16816(D[2 * g + 1], ah0, ah1, ah2, ah3, bh2, bh3);
            MMA16816(D[2 * g + 1], ah0, ah1, ah2, ah3, bl2, bl3);
            MMA16816(D[2 * g + 1], al0, al1, al2, al3, bh2, bh3);
        }
    }

    int r0 = m0 + 16 * w + (l >> 2);
    int r1 = r0 + 8;
#pragma unroll
    for (int nc = 0; nc < 8; nc++) {
        int col = nc * 8 + (l & 3) * 2;
        if (r0 < NN) *(__half2*)(g_Yh + (size_t)r0 * HID + col) = __floats2half2_rn(D[nc][0], D[nc][1]);
        if (r1 < NN) *(__half2*)(g_Yh + (size_t)r1 * HID + col) = __floats2half2_rn(D[nc][2], D[nc][3]);
    }
}

// ================================================================ k_mid via mma.sync
__global__ __launch_bounds__(256, 2) void k_mid_mma(
    const float* __restrict__ W1b, const float* __restrict__ b1b,
    const float* __restrict__ g1,  const float* __restrict__ be1,
    const float* __restrict__ m1,  const float* __restrict__ v1,
    const float* __restrict__ W2a)
{
    extern __shared__ char smc[];
    uint32_t sb = smem_u32(smc);
    float* scp = (float*)(smc + MD_SC);
    float* shp = (float*)(smc + MD_SH);
    int tid = threadIdx.x;
    int w = tid >> 5, l = tid & 31;
    int m0 = blockIdx.x * 128;

    // stage A = relu(g_A): batch 8 loads first
    {
        int row = tid >> 1, half = tid & 1;
        int gm = m0 + row;
        bool ok = gm < NN;
        const float4* ar = (const float4*)(g_A + (size_t)gm * HID + half * 32);
        int rbase = row * RST2 + half * 64;
        float4 ab[8];
#pragma unroll
        for (int j = 0; j < 8; j++)
            ab[j] = ok ? ar[j] : make_float4(0.f, 0.f, 0.f, 0.f);
#pragma unroll
        for (int c = 0; c < 4; c++) {
            float fv[8] = {fmaxf(ab[2*c].x, 0.f), fmaxf(ab[2*c].y, 0.f),
                           fmaxf(ab[2*c].z, 0.f), fmaxf(ab[2*c].w, 0.f),
                           fmaxf(ab[2*c+1].x, 0.f), fmaxf(ab[2*c+1].y, 0.f),
                           fmaxf(ab[2*c+1].z, 0.f), fmaxf(ab[2*c+1].w, 0.f)};
            uint32_t hp[4], lp[4];
            split8(fv, hp, lp);
            *(uint4*)(smc + MD_AH + rbase + c * 16) = make_uint4(hp[0], hp[1], hp[2], hp[3]);
            *(uint4*)(smc + MD_AL + rbase + c * 16) = make_uint4(lp[0], lp[1], lp[2], lp[3]);
        }
    }
    // stage W1b + W2a: batch 8 loads
    {
        int row = tid >> 2, q = tid & 3;
        const float4* w1r = (const float4*)(W1b + (size_t)row * HID + q * 16);
        const float4* w2r = (const float4*)(W2a + (size_t)row * HID + q * 16);
        float4 wb[8];
#pragma unroll
        for (int j = 0; j < 4; j++) { wb[j] = w1r[j]; wb[4 + j] = w2r[j]; }
#pragma unroll
        for (int c = 0; c < 2; c++) {
            int rb = row * RST2 + q * 32 + c * 16;
            float fv[8] = {wb[2*c].x, wb[2*c].y, wb[2*c].z, wb[2*c].w,
                           wb[2*c+1].x, wb[2*c+1].y, wb[2*c+1].z, wb[2*c+1].w};
            uint32_t hp[4], lp[4];
            split8(fv, hp, lp);
            *(uint4*)(smc + MD_W1H + rb) = make_uint4(hp[0], hp[1], hp[2], hp[3]);
            *(uint4*)(smc + MD_W1L + rb) = make_uint4(lp[0], lp[1], lp[2], lp[3]);
            float gv[8] = {wb[4+2*c].x, wb[4+2*c].y, wb[4+2*c].z, wb[4+2*c].w,
                           wb[4+2*c+1].x, wb[4+2*c+1].y, wb[4+2*c+1].z, wb[4+2*c+1].w};
            split8(gv, hp, lp);
            *(uint4*)(smc + MD_W2H + rb) = make_uint4(hp[0], hp[1], hp[2], hp[3]);
            *(uint4*)(smc + MD_W2L + rb) = make_uint4(lp[0], lp[1], lp[2], lp[3]);
        }
    }
    if (tid < HID) {
        float s = g1[tid] * rsqrtf(v1[tid] + BN_EPS_F);
        scp[tid] = s;
        shp[tid] = (b1b[tid] - m1[tid]) * s + be1[tid];
    }
    __syncthreads();

    uint32_t aAddr = sb + (uint32_t)((16 * w + (l & 15)) * RST2 + (l >> 4) * 16);
    int bN = (l & 7) + ((l >> 4) << 3);
    int bKc = (l >> 3) & 1;
    uint32_t bAddr = sb + (uint32_t)(bN * RST2 + bKc * 16);

    float D[8][4];
#pragma unroll
    for (int nc = 0; nc < 8; nc++)
#pragma unroll
        for (int j = 0; j < 4; j++) D[nc][j] = 0.f;

#pragma unroll
    for (int ks = 0; ks < 4; ks++) {
        uint32_t ko = ks * 32;
        uint32_t ah0, ah1, ah2, ah3, al0, al1, al2, al3;
        LDMX4(ah0, ah1, ah2, ah3, aAddr + MD_AH + ko);
        LDMX4(al0, al1, al2, al3, aAddr + MD_AL + ko);
#pragma unroll
        for (int g = 0; g < 4; g++) {
            uint32_t gb = bAddr + (uint32_t)(g * 16 * RST2) + ko;
            uint32_t bh0, bh1, bh2, bh3, bl0, bl1, bl2, bl3;
            LDMX4(bh0, bh1, bh2, bh3, gb + MD_W1H);
            LDMX4(bl0, bl1, bl2, bl3, gb + MD_W1L);
            MMA16816(D[2 * g],     ah0, ah1, ah2, ah3, bh0, bh1);
            MMA16816(D[2 * g],     ah0, ah1, ah2, ah3, bl0, bl1);
            MMA16816(D[2 * g],     al0, al1, al2, al3, bh0, bh1);
            MMA16816(D[2 * g + 1], ah0, ah1, ah2, ah3, bh2, bh3);
            MMA16816(D[2 * g + 1], ah0, ah1, ah2, ah3, bl2, bl3);
            MMA16816(D[2 * g + 1], al0, al1, al2, al3, bh2, bh3);
        }
    }

    uint32_t ahi[4][4], alo[4][4];
    {
        int t2 = (l & 3) * 2;
#pragma unroll
        for (int nc = 0; nc < 8; nc++) {
            int col = nc * 8 + t2;
            float s0 = scp[col], s1 = scp[col + 1];
            float t0 = shp[col], t1 = shp[col + 1];
            D[nc][0] = fmaxf(fmaf(D[nc][0], s0, t0), 0.f);
            D[nc][1] = fmaxf(fmaf(D[nc][1], s1, t1), 0.f);
            D[nc][2] = fmaxf(fmaf(D[nc][2], s0, t0), 0.f);
            D[nc][3] = fmaxf(fmaf(D[nc][3], s1, t1), 0.f);
        }
#pragma unroll
        for (int kc = 0; kc < 4; kc++) {
#pragma unroll
            for (int j = 0; j < 4; j++) {
                float h0 = D[2 * kc + (j >> 1)][(j & 1) * 2 + 0];
                float h1 = D[2 * kc + (j >> 1)][(j & 1) * 2 + 1];
                uint32_t hp;
                BF2(hp, h0, h1);
                float l0 = h0 - __uint_as_float(hp << 16);
                float l1 = h1 - __uint_as_float(hp & 0xFFFF0000u);
                uint32_t lp;
                BF2(lp, l0, l1);
                ahi[kc][j] = hp;
                alo[kc][j] = lp;
            }
        }
    }

    float D2[8][4];
#pragma unroll
    for (int nc = 0; nc < 8; nc++)
#pragma unroll
        for (int j = 0; j < 4; j++) D2[nc][j] = 0.f;

#pragma unroll
    for (int kc = 0; kc < 4; kc++) {
        uint32_t ko = kc * 32;
#pragma unroll
        for (int g = 0; g < 4; g++) {
            uint32_t gb = bAddr + (uint32_t)(g * 16 * RST2) + ko;
            uint32_t bh0, bh1, bh2, bh3, bl0, bl1, bl2, bl3;
            LDMX4(bh0, bh1, bh2, bh3, gb + MD_W2H);
            LDMX4(bl0, bl1, bl2, bl3, gb + MD_W2L);
            MMA16816(D2[2 * g],     ahi[kc][0], ahi[kc][1], ahi[kc][2], ahi[kc][3], bh0, bh1);
            MMA16816(D2[2 * g],     ahi[kc][0], ahi[kc][1], ahi[kc][2], ahi[kc][3], bl0, bl1);
            MMA16816(D2[2 * g],     alo[kc][0], alo[kc][1], alo[kc][2], alo[kc][3], bh0, bh1);
            MMA16816(D2[2 * g + 1], ahi[kc][0], ahi[kc][1], ahi[kc][2], ahi[kc][3], bh2, bh3);
            MMA16816(D2[2 * g + 1], ahi[kc][0], ahi[kc][1], ahi[kc][2], ahi[kc][3], bl2, bl3);
            MMA16816(D2[2 * g + 1], alo[kc][0], alo[kc][1], alo[kc][2], alo[kc][3], bh2, bh3);
        }
    }

    int r0 = m0 + 16 * w + (l >> 2);
    int r1 = r0 + 8;
#pragma unroll
    for (int nc = 0; nc < 8; nc++) {
        int col = nc * 8 + (l & 3) * 2;
        if (r0 < NN) *(__half2*)(g_Yh + (size_t)r0 * HID + col) = __floats2half2_rn(D2[nc][0], D2[nc][1]);
        if (r1 < NN) *(__half2*)(g_Yh + (size_t)r1 * HID + col) = __floats2half2_rn(D2[nc][2], D2[nc][3]);
    }
}

// ================================================================ k_final via mma.sync
__global__ __launch_bounds__(256, 2) void k_final_mma(
    const float* __restrict__ W2b, const float* __restrict__ bb,
    const float* __restrict__ ga,  const float* __restrict__ be,
    const float* __restrict__ mm,  const float* __restrict__ vv,
    const int* __restrict__ batch, float* __restrict__ out)
{
    extern __shared__ char smc[];
    uint32_t sb = smem_u32(smc);
    float* scp = (float*)(smc + FN_SC);
    float* shp = (float*)(smc + FN_SH);
    int tid = threadIdx.x;
    int w = tid >> 5, l = tid & 31;
    int m0 = blockIdx.x * 128;

    {
        int row = tid >> 1, half = tid & 1;
        int gm = m0 + row;
        bool ok = gm < NN;
        const float4* ar = (const float4*)(g_A + (size_t)gm * HID + half * 32);
        int rbase = row * RST2 + half * 64;
        float4 ab[8];
#pragma unroll
        for (int j = 0; j < 8; j++)
            ab[j] = ok ? ar[j] : make_float4(0.f, 0.f, 0.f, 0.f);
#pragma unroll
        for (int c = 0; c < 4; c++) {
            float fv[8] = {fmaxf(ab[2*c].x, 0.f), fmaxf(ab[2*c].y, 0.f),
                           fmaxf(ab[2*c].z, 0.f), fmaxf(ab[2*c].w, 0.f),
                           fmaxf(ab[2*c+1].x, 0.f), fmaxf(ab[2*c+1].y, 0.f),
                           fmaxf(ab[2*c+1].z, 0.f), fmaxf(ab[2*c+1].w, 0.f)};
            uint32_t hp[4], lp[4];
            split8(fv, hp, lp);
            *(uint4*)(smc + FN_AH + rbase + c * 16) = make_uint4(hp[0], hp[1], hp[2], hp[3]);
            *(uint4*)(smc + FN_AL + rbase + c * 16) = make_uint4(lp[0], lp[1], lp[2], lp[3]);
        }
    }
    {
        int row = tid >> 2, q = tid & 3;
        const float4* wr = (const float4*)(W2b + (size_t)row * HID + q * 16);
        float4 wb[4];
#pragma unroll
        for (int j = 0; j < 4; j++) wb[j] = wr[j];
#pragma unroll
        for (int c = 0; c < 2; c++) {
            int rb = row * RST2 + q * 32 + c * 16;
            float fv[8] = {wb[2*c].x, wb[2*c].y, wb[2*c].z, wb[2*c].w,
                           wb[2*c+1].x, wb[2*c+1].y, wb[2*c+1].z, wb[2*c+1].w};
            uint32_t hp[4], lp[4];
            split8(fv, hp, lp);
            *(uint4*)(smc + FN_WH + rb) = make_uint4(hp[0], hp[1], hp[2], hp[3]);
            *(uint4*)(smc + FN_WL + rb) = make_uint4(lp[0], lp[1], lp[2], lp[3]);
        }
    }
    if (tid < HID) {
        float s = ga[tid] * rsqrtf(vv[tid] + BN_EPS_F);
        scp[tid] = s;
        shp[tid] = (bb[tid] - mm[tid]) * s + be[tid];
    }
    __syncthreads();

    uint32_t aAddr = sb + (uint32_t)((16 * w + (l & 15)) * RST2 + (l >> 4) * 16);
    int bN = (l & 7) + ((l >> 4) << 3);
    int bKc = (l >> 3) & 1;
    uint32_t bAddr = sb + (uint32_t)(bN * RST2 + bKc * 16);

    float D[8][4];
#pragma unroll
    for (int nc = 0; nc < 8; nc++)
#pragma unroll
        for (int j = 0; j < 4; j++) D[nc][j] = 0.f;

#pragma unroll
    for (int ks = 0; ks < 4; ks++) {
        uint32_t ko = ks * 32;
        uint32_t ah0, ah1, ah2, ah3, al0, al1, al2, al3;
        LDMX4(ah0, ah1, ah2, ah3, aAddr + FN_AH + ko);
        LDMX4(al0, al1, al2, al3, aAddr + FN_AL + ko);
#pragma unroll
        for (int g = 0; g < 4; g++) {
            uint32_t gb = bAddr + (uint32_t)(g * 16 * RST2) + ko;
            uint32_t bh0, bh1, bh2, bh3, bl0, bl1, bl2, bl3;
            LDMX4(bh0, bh1, bh2, bh3, gb + FN_WH);
            LDMX4(bl0, bl1, bl2, bl3, gb + FN_WL);
            MMA16816(D[2 * g],     ah0, ah1, ah2, ah3, bh0, bh1);
            MMA16816(D[2 * g],     ah0, ah1, ah2, ah3, bl0, bl1);
            MMA16816(D[2 * g],     al0, al1, al2, al3, bh0, bh1);
            MMA16816(D[2 * g + 1], ah0, ah1, ah2, ah3, bh2, bh3);
            MMA16816(D[2 * g + 1], ah0, ah1, ah2, ah3, bl2, bl3);
            MMA16816(D[2 * g + 1], al0, al1, al2, al3, bh2, bh3);
        }
    }

    int r0 = m0 + 16 * w + (l >> 2);
    int r1 = r0 + 8;
    int gb0 = (r0 < NN) ? batch[r0] : 0;
    int gb1 = (r1 < NN) ? batch[r1] : 0;
    int t2 = (l & 3) * 2;
#pragma unroll
    for (int nc = 0; nc < 8; nc++) {
        int col = nc * 8 + t2;
        float s0 = scp[col], s1 = scp[col + 1];
        float t0 = shp[col], t1 = shp[col + 1];
        if (r0 < NN)
            red_add_v2(out + (size_t)gb0 * HID + col,
                       fmaxf(fmaf(D[nc][0], s0, t0), 0.f),
                       fmaxf(fmaf(D[nc][1], s1, t1), 0.f));
        if (r1 < NN)
            red_add_v2(out + (size_t)gb1 * HID + col,
                       fmaxf(fmaf(D[nc][2], s0, t0), 0.f),
                       fmaxf(fmaf(D[nc][3], s1, t1), 0.f));
    }
}

// ------------------------------------------------- divide by per-graph counts
__global__ void k_div(const int* __restrict__ batch, float* __restrict__ out)
{
    int g = blockIdx.x;
    __shared__ int cnt;
    if (threadIdx.x == 0) {
        int lo = 0, hi = NN;
        while (lo < hi) { int mid = (lo + hi) >> 1; if (batch[mid] < g) lo = mid + 1; else hi = mid; }
        int lo2 = lo, hi2 = NN;
        while (lo2 < hi2) { int mid = (lo2 + hi2) >> 1; if (batch[mid] < g + 1) lo2 = mid + 1; else hi2 = mid; }
        cnt = lo2 - lo;
    }
    __syncthreads();
    float c = (float)(cnt > 1 ? cnt : 1);
    out[(size_t)g * HID + threadIdx.x] /= c;
}

// ---------------------------------------------------------------- launch
extern "C" void kernel_launch(void* const* d_in, const int* in_sizes, int n_in,
                              void* d_out, int out_size)
{
    (void)in_sizes; (void)n_in; (void)out_size;
    const float* x    = (const float*)d_in[0];
    const int*   ei   = (const int*)d_in[1];
    const int*   batch= (const int*)d_in[2];
    const float* W1a  = (const float*)d_in[3];
    const float* b1a  = (const float*)d_in[4];
    const float* W1b  = (const float*)d_in[5];
    const float* b1b  = (const float*)d_in[6];
    const float* g1   = (const float*)d_in[7];
    const float* be1  = (const float*)d_in[8];
    const float* m1   = (const float*)d_in[9];
    const float* v1   = (const float*)d_in[10];
    const float* W2a  = (const float*)d_in[11];
    const float* b2a  = (const float*)d_in[12];
    const float* W2b  = (const float*)d_in[13];
    const float* b2b  = (const float*)d_in[14];
    const float* g2   = (const float*)d_in[15];
    const float* be2  = (const float*)d_in[16];
    const float* m2   = (const float*)d_in[17];
    const float* v2   = (const float*)d_in[18];
    float* out = (float*)d_out;

    static cudaStream_t s2 = nullptr;
    static cudaEvent_t ev0 = nullptr, evA = nullptr;
    if (!s2) {
        cudaStreamCreateWithFlags(&s2, cudaStreamNonBlocking);
        cudaEventCreateWithFlags(&ev0, cudaEventDisableTiming);
        cudaEventCreateWithFlags(&evA, cudaEventDisableTiming);
    }

    cudaFuncSetAttribute(k_in_proj_mma, cudaFuncAttributeMaxDynamicSharedMemorySize, MMA_SMEM);
    cudaFuncSetAttribute(k_mid_mma,     cudaFuncAttributeMaxDynamicSharedMemorySize, MD_SMEM);
    cudaFuncSetAttribute(k_final_mma,   cudaFuncAttributeMaxDynamicSharedMemorySize, FN_SMEM);

    int gemmBlocks = (NN + 127) / 128;             // 782
    int edgeBlocks = (EE + 255) / 256;             // 6250
    int aggBlocks  = (NN * 8 + 255) / 256;         // 3125

    // fork: in_proj concurrent with CSR build
    cudaEventRecord(ev0, 0);
    cudaStreamWaitEvent(s2, ev0, 0);
    k_in_proj_mma<<<gemmBlocks, 256, MMA_SMEM, s2>>>(x, W1a);
    cudaEventRecord(evA, s2);

    k_zero_all<<<(NN + 255) / 256, 256>>>(out);
    k_hist<<<edgeBlocks, 256>>>(ei);
    k_scan1<<<NCHUNK, SCAN_CHUNK>>>();
    k_scan3f<<<(NN + 255) / 256, 256>>>();
    k_reorder<<<edgeBlocks, 256>>>(ei);

    cudaStreamWaitEvent(0, evA, 0);

    // layer 1 + mid
    k_agg<<<aggBlocks, 256>>>(b1a);
    k_mid_mma<<<gemmBlocks, 256, MD_SMEM>>>(W1b, b1b, g1, be1, m1, v1, W2a);

    // layer 2
    k_agg<<<aggBlocks, 256>>>(b2a);
    k_final_mma<<<gemmBlocks, 256, FN_SMEM>>>(W2b, b2b, g2, be2, m2, v2, batch, out);
    k_div<<<NG, HID>>>(batch, out);
}